// round 2
// baseline (speedup 1.0000x reference)
#include <cuda_runtime.h>
#include <math.h>

// Problem geometry
#define N_IMG 64
#define IMG_ELEMS 786432               // 512*512*3
#define IMG_VEC4  196608               // IMG_ELEMS / 4
#define BLOCKS_PER_IMG 24
#define CHUNK_ELEMS (IMG_ELEMS / BLOCKS_PER_IMG)   // 32768
#define CHUNK_VEC4  (CHUNK_ELEMS / 4)              // 8192
#define RED_THREADS 256

// Scratch (no allocations allowed in kernel_launch)
__device__ float2 g_partials[N_IMG * BLOCKS_PER_IMG];
__device__ float2 g_scale_shift[N_IMG];   // x = scale, y = shift

// -------- Kernel 1: per-chunk partial (sum, sumsq) --------
__global__ __launch_bounds__(RED_THREADS)
void partial_reduce_kernel(const float* __restrict__ in) {
    const int img   = blockIdx.x / BLOCKS_PER_IMG;
    const int chunk = blockIdx.x % BLOCKS_PER_IMG;
    const float4* __restrict__ p =
        reinterpret_cast<const float4*>(in) +
        (size_t)img * IMG_VEC4 + (size_t)chunk * CHUNK_VEC4;

    float s = 0.f, sq = 0.f;
    #pragma unroll 8
    for (int i = threadIdx.x; i < CHUNK_VEC4; i += RED_THREADS) {
        float4 v = __ldg(p + i);
        s  += (v.x + v.y) + (v.z + v.w);
        sq += (v.x * v.x + v.y * v.y) + (v.z * v.z + v.w * v.w);
    }

    // warp reduce
    #pragma unroll
    for (int off = 16; off > 0; off >>= 1) {
        s  += __shfl_down_sync(0xffffffffu, s,  off);
        sq += __shfl_down_sync(0xffffffffu, sq, off);
    }
    __shared__ float2 warp_red[RED_THREADS / 32];
    const int lane = threadIdx.x & 31, wid = threadIdx.x >> 5;
    if (lane == 0) warp_red[wid] = make_float2(s, sq);
    __syncthreads();
    if (wid == 0) {
        float2 v = (lane < RED_THREADS / 32) ? warp_red[lane] : make_float2(0.f, 0.f);
        s = v.x; sq = v.y;
        #pragma unroll
        for (int off = 4; off > 0; off >>= 1) {
            s  += __shfl_down_sync(0xffffffffu, s,  off);
            sq += __shfl_down_sync(0xffffffffu, sq, off);
        }
        if (lane == 0) g_partials[blockIdx.x] = make_float2(s, sq);
    }
}

// -------- Kernel 2: finalize stats -> (scale, shift) per image --------
__global__ void finalize_kernel() {
    const int img  = blockIdx.x;
    const int lane = threadIdx.x;  // 32 threads
    float s = 0.f, sq = 0.f;
    if (lane < BLOCKS_PER_IMG) {
        float2 v = g_partials[img * BLOCKS_PER_IMG + lane];
        s = v.x; sq = v.y;
    }
    #pragma unroll
    for (int off = 16; off > 0; off >>= 1) {
        s  += __shfl_down_sync(0xffffffffu, s,  off);
        sq += __shfl_down_sync(0xffffffffu, sq, off);
    }
    if (lane == 0) {
        const float inv_n = 1.0f / (float)IMG_ELEMS;
        float mean = s * inv_n;
        float var  = sq * inv_n - mean * mean;
        float stddev = sqrtf(fmaxf(var, 0.0f));
        const float min_std = 1.0f / sqrtf((float)IMG_ELEMS);  // 1/sqrt(786432)
        float adj = fmaxf(stddev, min_std);
        float scale = 1.0f / adj;
        g_scale_shift[img] = make_float2(scale, -mean * scale);
    }
}

// -------- Kernel 3: apply out = in*scale + shift --------
__global__ __launch_bounds__(256)
void apply_kernel(const float* __restrict__ in, float* __restrict__ out) {
    const unsigned idx = blockIdx.x * 256u + threadIdx.x;   // one float4 per thread
    const unsigned img = idx / IMG_VEC4;
    const float2 ss = g_scale_shift[img];
    float4 v = __ldg(reinterpret_cast<const float4*>(in) + idx);
    float4 r;
    r.x = fmaf(v.x, ss.x, ss.y);
    r.y = fmaf(v.y, ss.x, ss.y);
    r.z = fmaf(v.z, ss.x, ss.y);
    r.w = fmaf(v.w, ss.x, ss.y);
    reinterpret_cast<float4*>(out)[idx] = r;
}

extern "C" void kernel_launch(void* const* d_in, const int* in_sizes, int n_in,
                              void* d_out, int out_size) {
    const float* in = (const float*)d_in[0];
    float* out = (float*)d_out;

    partial_reduce_kernel<<<N_IMG * BLOCKS_PER_IMG, RED_THREADS>>>(in);
    finalize_kernel<<<N_IMG, 32>>>();
    const unsigned total_vec4 = (unsigned)N_IMG * IMG_VEC4;   // 12,582,912
    apply_kernel<<<total_vec4 / 256, 256>>>(in, out);
}